// round 10
// baseline (speedup 1.0000x reference)
#include <cuda_runtime.h>
#include <math.h>
#include <float.h>

#define BB 32
#define QQ 900
#define MM 128
#define KC 80
#define KP1 81
#define NT 8                       // q-tiles per image (8*128 >= 900)
#define INFF __int_as_float(0x7f800000)
#define DEAD64 0xffffffffffffffffull
#define DEADHI 0xffffffffu
#define FULL 0xffffffffu

// scratch (no allocations allowed -> __device__ globals)
__device__ float g_costT[BB * MM * QQ];                 // 14.7 MB [b][m][q]
__device__ unsigned long long g_top[BB * NT * MM * 4];  // per-tile column top-4
__device__ float g_lse[BB * QQ];
__device__ float g_b80[BB * QQ];                        // lse - logit[q][80]
__device__ float g_acc[3];
__device__ unsigned g_done;

// monotone float->uint mapping (preserves < ordering)
__device__ __forceinline__ unsigned ford(float f) {
    unsigned u = __float_as_uint(f);
    return u ^ ((u >> 31) ? 0xffffffffu : 0x80000000u);
}

// ---------------- kernel A: softmax + cost tile + per-tile column top-4 --------
// grid (NT, B), block 128.
__global__ void __launch_bounds__(128) k_costT(
    const float* __restrict__ logits,
    const float* __restrict__ pboxes,
    const float* __restrict__ tboxes,
    const float* __restrict__ sizes,
    const int*   __restrict__ labels) {
    int b = blockIdx.y, tid = threadIdx.x;
    int q0 = blockIdx.x * 128;
    int q = q0 + tid;
    __shared__ float sprob[128 * KP1];       // 41.5 KB
    __shared__ float tn0[MM], tn1[MM], tn2[MM], tn3[MM], tc[MM], ts[MM];
    __shared__ int   tl[MM];
    __shared__ float pq0[128], pq1[128], pq2[128], pq3[128], pqc[128], pqs[128];

    if (b == 0 && blockIdx.x == 0 && tid < 4) {
        if (tid < 3) g_acc[tid] = 0.f; else g_done = 0u;
    }

    float H = sizes[b * 2 + 0], W = sizes[b * 2 + 1];
    {   // tid doubles as target index m
        const float* tb = tboxes + ((size_t)b * MM + tid) * 5;
        tn0[tid] = tb[0] / W; tn1[tid] = tb[1] / H;
        tn2[tid] = tb[2] / W; tn3[tid] = tb[3] / H;
        float sn, cs; sincosf(tb[4], &sn, &cs);
        tc[tid] = cs; ts[tid] = sn;
        tl[tid] = labels[b * MM + tid];
    }
    int nrow = min(128, QQ - q0);
    int tot = nrow * KP1;
    const float* lg0 = logits + ((size_t)b * QQ + q0) * KP1;
    for (int i = tid; i < tot; i += 128) sprob[i] = lg0[i];
    __syncthreads();

    bool valid = q < QQ;
    if (valid) {
        float* r = sprob + tid * KP1;        // stride 81: bank-conflict-free
        float l80 = r[KC];
        float mx = -FLT_MAX;
#pragma unroll 9
        for (int k = 0; k < KP1; k++) mx = fmaxf(mx, r[k]);
        float s = 0.f;
#pragma unroll 9
        for (int k = 0; k < KP1; k++) { float e = __expf(r[k] - mx); r[k] = e; s += e; }
        float inv = 1.f / s;
#pragma unroll 9
        for (int k = 0; k < KP1; k++) r[k] *= inv;
        float lse = mx + __logf(s);
        g_lse[b * QQ + q] = lse;
        g_b80[b * QQ + q] = lse - l80;
        const float* pb = pboxes + ((size_t)b * QQ + q) * 5;
        float sn, cs; sincosf(pb[4], &sn, &cs);
        pq0[tid] = pb[0]; pq1[tid] = pb[1]; pq2[tid] = pb[2]; pq3[tid] = pb[3];
        pqc[tid] = cs; pqs[tid] = sn;
    }
    __syncthreads();

    // ---- write transposed cost tile (thread = q, coalesced along q) ----
    if (valid) {
        float p0 = pq0[tid], p1 = pq1[tid], p2 = pq2[tid], p3 = pq3[tid];
        float pc = pqc[tid], psn = pqs[tid];
        const float* r = sprob + tid * KP1;
        float* outb = g_costT + (size_t)b * MM * QQ + q;
#pragma unroll 4
        for (int m = 0; m < MM; m++) {
            float prob = r[tl[m]];
            float l1 = fabsf(p0 - tn0[m]) + fabsf(p1 - tn1[m]) +
                       fabsf(p2 - tn2[m]) + fabsf(p3 - tn3[m]);
            float cosd = pc * tc[m] + psn * ts[m];
            outb[(size_t)m * QQ] = -2.f * prob + 5.f * l1 + 2.f * (1.f - cosd);
        }
    }

    // ---- per-tile column top-4 (thread = m, recompute from smem) ----
    {
        int m = tid;
        float t0 = tn0[m], t1 = tn1[m], t2 = tn2[m], t3 = tn3[m];
        float tcc = tc[m], tss = ts[m];
        int lab = tl[m];
        unsigned long long e0 = DEAD64, e1 = DEAD64, e2 = DEAD64, e3 = DEAD64;
        for (int j = 0; j < nrow; j++) {
            float prob = sprob[j * KP1 + lab];
            float l1 = fabsf(pq0[j] - t0) + fabsf(pq1[j] - t1) +
                       fabsf(pq2[j] - t2) + fabsf(pq3[j] - t3);
            float cosd = pqc[j] * tcc + pqs[j] * tss;
            float v = -2.f * prob + 5.f * l1 + 2.f * (1.f - cosd);
            unsigned long long k = ((unsigned long long)ford(v) << 32) | (unsigned)(q0 + j);
            if (k < e3) {
                if (k < e0)      { e3 = e2; e2 = e1; e1 = e0; e0 = k; }
                else if (k < e1) { e3 = e2; e2 = e1; e1 = k; }
                else if (k < e2) { e3 = e2; e2 = k; }
                else             { e3 = k; }
            }
        }
        size_t idx = (((size_t)b * NT + blockIdx.x) * MM + m) * 4;
        g_top[idx + 0] = e0; g_top[idx + 1] = e1;
        g_top[idx + 2] = e2; g_top[idx + 3] = e3;
    }
}

// shift head of group G from register tail (DEAD64 tail auto-produces DEADHI head)
#define SHIFT(G) { hh[G] = (unsigned)(t1[G] >> 32); hq[G] = (unsigned)t1[G] & 0x3ffu; \
                   t1[G] = t2[G]; t2[G] = t3[G]; t3[G] = DEAD64; }

// ---------------- kernel B: match (warp0, lazy validation) + loss baseline -----
__global__ void __launch_bounds__(256, 1) k_match_loss(
    const float* __restrict__ logits,
    const float* __restrict__ pboxes,
    const float* __restrict__ tboxes,
    const float* __restrict__ sizes,
    const int*   __restrict__ labels,
    float* __restrict__ out) {
    int b = blockIdx.x, tid = threadIdx.x;
    int lane = tid & 31, wid = tid >> 5;
    __shared__ unsigned long long ce[MM][4];
    __shared__ float    rmask[1024];   // 0 = free row, +INF = used (padded)
    __shared__ short    sq[MM], sm[MM];
    __shared__ float    sb80[QQ];
    __shared__ float    wsum[8];
    __shared__ float    buf[256];
    const float* C = g_costT + (size_t)b * MM * QQ;

    for (int q = tid; q < 1024; q += 256) rmask[q] = 0.f;

    // ---- merge 8 per-tile top-4 lists into exact global top-4 per column ----
    if (tid < MM) {
        const unsigned long long* p = g_top + ((size_t)b * NT * MM + tid) * 4;
        unsigned long long e0 = DEAD64, e1 = DEAD64, e2 = DEAD64, e3 = DEAD64;
#pragma unroll
        for (int t = 0; t < NT; t++) {
#pragma unroll
            for (int r = 0; r < 4; r++) {
                unsigned long long k = p[(size_t)t * MM * 4 + r];
                if (k < e3) {
                    if (k < e0)      { e3 = e2; e2 = e1; e1 = e0; e0 = k; }
                    else if (k < e1) { e3 = e2; e2 = e1; e1 = k; }
                    else if (k < e2) { e3 = e2; e2 = k; }
                    else             { e3 = k; }
                }
            }
        }
        ce[tid][0] = e0; ce[tid][1] = e1; ce[tid][2] = e2; ce[tid][3] = e3;
    }
    __syncthreads();

    if (wid == 0) {
        // ========== matching loop: single REDUX commits, lazy validation ======
        unsigned hh[4], hq[4];
        unsigned long long t1[4], t2[4], t3[4];
#pragma unroll
        for (int g = 0; g < 4; g++) {
            unsigned long long k = ce[lane + 32 * g][0];
            hh[g] = (unsigned)(k >> 32); hq[g] = (unsigned)k & 0x3ffu;
            t1[g] = ce[lane + 32 * g][1];
            t2[g] = ce[lane + 32 * g][2];
            t3[g] = ce[lane + 32 * g][3];
        }

        int it = 0, nc = 0, rf = 0;
        unsigned myrq = 0xffffffffu;
        while (it < MM) {
            // ---- per-lane best over 4 groups (32-bit lex compare) ----
            unsigned bv = hh[0], bq = hq[0]; int bg = 0;
            if (hh[1] < bv || (hh[1] == bv && hq[1] < bq)) { bv = hh[1]; bq = hq[1]; bg = 1; }
            if (hh[2] < bv || (hh[2] == bv && hq[2] < bq)) { bv = hh[2]; bq = hq[2]; bg = 2; }
            if (hh[3] < bv || (hh[3] == bv && hq[3] < bq)) { bv = hh[3]; bq = hq[3]; bg = 3; }
            unsigned umin = __reduce_min_sync(FULL, bv);

            if (umin == DEADHI) {
                // all heads dead: flush batch, rescan flagged columns exactly
                if (lane < nc) rmask[myrq] = INFF;
                nc = 0; myrq = 0xffffffffu;
                __syncwarp();
#pragma unroll
                for (int g = 0; g < 4; g++) {
                    unsigned bal = __ballot_sync(FULL, (rf >> g) & 1);
                    while (bal) {
                        int c = __ffs(bal) - 1; bal &= bal - 1;
                        int mr = c + 32 * g;
                        const float* col = C + (size_t)mr * QQ;
                        float nv = INFF; int nq = 0x3ff;
#pragma unroll 7
                        for (int j = 0; j < 28; j++) {
                            int q2 = lane + 32 * j;
                            float v = col[q2] + rmask[q2];
                            if (v < nv) { nv = v; nq = q2; }
                        }
                        { int q2 = lane + 896; if (q2 < QQ) { float v = col[q2] + rmask[q2]; if (v < nv) { nv = v; nq = q2; } } }
                        unsigned uu = ford(nv);
                        unsigned um = __reduce_min_sync(FULL, uu);
                        unsigned qq = (uu == um) ? (unsigned)nq : 0xffffffffu;
                        unsigned qmn = __reduce_min_sync(FULL, qq);
                        if (lane == c) {
                            hh[g] = um; hq[g] = qmn;
                            t1[g] = DEAD64; t2[g] = DEAD64; t3[g] = DEAD64;
                            rf &= ~(1 << g);
                        }
                        __syncwarp();
                    }
                }
                continue;
            }

            // ---- identify winner (value, q, m) ----
            unsigned bal = __ballot_sync(FULL, bv == umin);
            unsigned qs, msu;
            if (__popc(bal) == 1) {
                int src = __ffs(bal) - 1;
                unsigned k = __shfl_sync(FULL, (bq << 7) | ((unsigned)bg << 5) | (unsigned)lane, src);
                qs = k >> 7; msu = k & 127u;
            } else {
                unsigned k = (bv == umin) ? ((bq << 7) | ((unsigned)bg << 5) | (unsigned)lane)
                                          : 0xffffffffu;
                unsigned kmin = __reduce_min_sync(FULL, k);
                qs = kmin >> 7; msu = kmin & 127u;
            }
            int ms = (int)msu;

            // ---- validate: row free of rmask and of current batch ----
            bool stale = rmask[qs] != 0.f;            // uniform broadcast read
            unsigned cb = __ballot_sync(FULL, lane < nc && myrq == qs);
            if (!stale && !cb) {
                // commit
                if (lane == 0) { sq[it] = (short)qs; sm[it] = (short)ms; }
                if (lane == nc) myrq = qs;
                if (lane == (ms & 31)) {
                    switch (ms >> 5) {               // kill consumed column
                        case 0: hh[0] = DEADHI; break;
                        case 1: hh[1] = DEADHI; break;
                        case 2: hh[2] = DEADHI; break;
                        default: hh[3] = DEADHI; break;
                    }
                }
                it++; nc++;
                if (nc == 32) {
                    if (lane < nc) rmask[myrq] = INFF;
                    nc = 0; myrq = 0xffffffffu;
                    __syncwarp();
                }
                continue;
            }

            // ---- advance stale winner column ms past dead rows ----
            {
                int c = ms & 31, gg = ms >> 5;
                for (;;) {
                    if (lane == c) {
                        switch (gg) {
                            case 0: SHIFT(0); break;
                            case 1: SHIFT(1); break;
                            case 2: SHIFT(2); break;
                            default: SHIFT(3); break;
                        }
                    }
                    unsigned myq;
                    switch (gg) {
                        case 0: myq = hq[0]; break;
                        case 1: myq = hq[1]; break;
                        case 2: myq = hq[2]; break;
                        default: myq = hq[3]; break;
                    }
                    unsigned nq = __shfl_sync(FULL, myq, c);
                    unsigned myh;
                    switch (gg) {
                        case 0: myh = hh[0]; break;
                        case 1: myh = hh[1]; break;
                        case 2: myh = hh[2]; break;
                        default: myh = hh[3]; break;
                    }
                    unsigned dead = __ballot_sync(FULL, lane == c && myh == DEADHI);
                    if (dead) { if (lane == c) rf |= (1 << gg); break; }
                    bool st2 = rmask[nq] != 0.f;
                    unsigned cb2 = __ballot_sync(FULL, lane < nc && myrq == nq);
                    if (!st2 && !cb2) break;
                }
            }
        }
    } else {
        // ============ warps 1-7: CE baseline (coalesced b80 load) =============
        float base = 0.f;
        for (int q = tid - 32; q < QQ; q += 224) {
            float v = g_b80[b * QQ + q];
            sb80[q] = v;
            base += v;
        }
        for (int o = 16; o; o >>= 1) base += __shfl_xor_sync(FULL, base, o);
        if (lane == 0) wsum[wid] = 0.1f * base;
    }
    __syncthreads();

    // ---- matched corrections (128 threads) ----
    float corr = 0.f, sb = 0.f, sa = 0.f;
    if (tid < MM) {
        int q = sq[tid], m = sm[tid];
        int lab = labels[b * MM + m];
        int row = b * QQ + q;
        corr = (g_lse[row] - logits[(size_t)row * KP1 + lab]) - 0.1f * sb80[q];
        float H = sizes[b * 2 + 0], W = sizes[b * 2 + 1];
        const float* pb = pboxes + ((size_t)b * QQ + q) * 5;
        const float* tb = tboxes + ((size_t)b * MM + m) * 5;
        sb = fabsf(pb[0] - tb[0] / W) + fabsf(pb[1] - tb[1] / H) +
             fabsf(pb[2] - tb[2] / W) + fabsf(pb[3] - tb[3] / H);
        sa = 1.f - cosf(pb[4] - tb[4]);
    }

    buf[tid] = corr; __syncthreads();
    for (int s = 128; s > 0; s >>= 1) { if (tid < s) buf[tid] += buf[tid + s]; __syncthreads(); }
    float numt = buf[0]; __syncthreads();
    buf[tid] = sb; __syncthreads();
    for (int s = 128; s > 0; s >>= 1) { if (tid < s) buf[tid] += buf[tid + s]; __syncthreads(); }
    float sbt = buf[0]; __syncthreads();
    buf[tid] = sa; __syncthreads();
    for (int s = 128; s > 0; s >>= 1) { if (tid < s) buf[tid] += buf[tid + s]; __syncthreads(); }
    float sat = buf[0];

    if (tid == 0) {
#pragma unroll
        for (int w = 1; w < 8; w++) numt += wsum[w];
        atomicAdd(&g_acc[0], numt);
        atomicAdd(&g_acc[1], sbt);
        atomicAdd(&g_acc[2], sat);
        __threadfence();
        unsigned done = atomicAdd(&g_done, 1u);
        if (done == BB - 1) {
            const float den = 0.1f * (QQ - MM) + (float)MM;   // 205.2 per image
            float lc = g_acc[0] / (den * BB);
            float lb = g_acc[1] * 5.f / (float)(MM * 4 * BB);
            float la = g_acc[2] * 2.f / (float)(MM * BB);
            out[0] = lc;
            out[1] = lb;
            out[2] = la;
            out[3] = lc + lb + la;
        }
    }
}

extern "C" void kernel_launch(void* const* d_in, const int* in_sizes, int n_in,
                              void* d_out, int out_size) {
    const float* logits = (const float*)d_in[0];   // [B,Q,81]
    const float* pboxes = (const float*)d_in[1];   // [B,Q,5]
    const float* tboxes = (const float*)d_in[2];   // [B,M,5]
    const float* sizes  = (const float*)d_in[3];   // [B,2]
    const int*   labels = (const int*)d_in[4];     // [B,M]
    float* out = (float*)d_out;

    dim3 gc(NT, BB);
    k_costT<<<gc, 128>>>(logits, pboxes, tboxes, sizes, labels);
    k_match_loss<<<BB, 256>>>(logits, pboxes, tboxes, sizes, labels, out);
}

// round 11
// speedup vs baseline: 1.4106x; 1.4106x over previous
#include <cuda_runtime.h>
#include <math.h>
#include <float.h>

#define BB 32
#define QQ 900
#define MM 128
#define KC 80
#define KP1 81
#define NT 8                       // q-tiles per image
#define INFF __int_as_float(0x7f800000)
#define DEAD64 0xffffffffffffffffull
#define FULL 0xffffffffu

// scratch (no allocations allowed -> __device__ globals)
__device__ float g_costT[BB * MM * QQ];                 // 14.7 MB [b][m][q]
__device__ unsigned long long g_top[BB * NT * MM * 4];  // per-tile column top-4
__device__ float g_lse[BB * QQ];
__device__ float g_b80[BB * QQ];                        // lse - logit[q][80]
__device__ float g_acc[3];
__device__ unsigned g_done;
__device__ unsigned g_ready[BB];

// monotone float->uint mapping (preserves < ordering)
__device__ __forceinline__ unsigned ford(float f) {
    unsigned u = __float_as_uint(f);
    return u ^ ((u >> 31) ? 0xffffffffu : 0x80000000u);
}

// dynamic smem: cost path needs 256*81*4 + 6*128*4 + 128*4 + 6*256*4 = 92672 B
#define SMEM_TOTAL 93184

__global__ void __launch_bounds__(256) k_fused(
    const float* __restrict__ logits,
    const float* __restrict__ pboxes,
    const float* __restrict__ tboxes,
    const float* __restrict__ sizes,
    const int*   __restrict__ labels,
    float* __restrict__ out) {
    extern __shared__ char smraw[];
    int bid = blockIdx.x, tid = threadIdx.x;

    if (bid < BB * 4) {
        // ================= COST BLOCK: image b, 2 q-tiles =====================
        int b = bid >> 2, pair = bid & 3;
        int q0 = pair * 256;
        int nrow = min(256, QQ - q0);
        float* sprob = (float*)smraw;                 // 256*81 floats
        float* tn0 = sprob + 256 * KP1;
        float* tn1 = tn0 + MM; float* tn2 = tn1 + MM; float* tn3 = tn2 + MM;
        float* tc  = tn3 + MM; float* ts  = tc  + MM;
        int*   tl  = (int*)(ts + MM);
        float* pq0 = (float*)(tl + MM);
        float* pq1 = pq0 + 256; float* pq2 = pq1 + 256; float* pq3 = pq2 + 256;
        float* pqc = pq3 + 256; float* pqs = pqc + 256;

        float H = sizes[b * 2 + 0], W = sizes[b * 2 + 1];
        if (tid < MM) {
            const float* tb = tboxes + ((size_t)b * MM + tid) * 5;
            tn0[tid] = tb[0] / W; tn1[tid] = tb[1] / H;
            tn2[tid] = tb[2] / W; tn3[tid] = tb[3] / H;
            float sn, cs; sincosf(tb[4], &sn, &cs);
            tc[tid] = cs; ts[tid] = sn;
            tl[tid] = labels[b * MM + tid];
        }
        int tot = nrow * KP1;
        const float* lg0 = logits + ((size_t)b * QQ + q0) * KP1;
        for (int i = tid; i < tot; i += 256) sprob[i] = lg0[i];
        __syncthreads();

        bool valid = tid < nrow;
        float p0 = 0, p1 = 0, p2 = 0, p3 = 0, pc = 0, psn = 0;
        if (valid) {
            float* r = sprob + tid * KP1;             // stride 81: conflict-free
            float l80 = r[KC];
            float mx = -FLT_MAX;
#pragma unroll 9
            for (int k = 0; k < KP1; k++) mx = fmaxf(mx, r[k]);
            float s = 0.f;
#pragma unroll 9
            for (int k = 0; k < KP1; k++) { float e = __expf(r[k] - mx); r[k] = e; s += e; }
            float inv = 1.f / s;
#pragma unroll 9
            for (int k = 0; k < KP1; k++) r[k] *= inv;
            float lse = mx + __logf(s);
            int q = q0 + tid;
            g_lse[b * QQ + q] = lse;
            g_b80[b * QQ + q] = lse - l80;
            const float* pb = pboxes + ((size_t)b * QQ + q) * 5;
            float sn, cs; sincosf(pb[4], &sn, &cs);
            p0 = pb[0]; p1 = pb[1]; p2 = pb[2]; p3 = pb[3]; pc = cs; psn = sn;
            pq0[tid] = p0; pq1[tid] = p1; pq2[tid] = p2; pq3[tid] = p3;
            pqc[tid] = cs; pqs[tid] = sn;
        }
        __syncthreads();

        // ---- transposed cost tile (thread = q, coalesced along q) ----
        if (valid) {
            const float* r = sprob + tid * KP1;
            float* outb = g_costT + (size_t)b * MM * QQ + (q0 + tid);
#pragma unroll 4
            for (int m = 0; m < MM; m++) {
                float prob = r[tl[m]];
                float l1 = fabsf(p0 - tn0[m]) + fabsf(p1 - tn1[m]) +
                           fabsf(p2 - tn2[m]) + fabsf(p3 - tn3[m]);
                float cosd = pc * tc[m] + psn * ts[m];
                outb[(size_t)m * QQ] = -2.f * prob + 5.f * l1 + 2.f * (1.f - cosd);
            }
        }

        // ---- per-tile column top-4: thread = (m, half-tile) ----
        {
            int m = tid & 127;
            int half = tid >> 7;
            int jb = half * 128;
            int je = min(jb + 128, nrow);
            int tile = pair * 2 + half;
            float t0 = tn0[m], t1 = tn1[m], t2 = tn2[m], t3 = tn3[m];
            float tcc = tc[m], tss = ts[m];
            int lab = tl[m];
            unsigned long long e0 = DEAD64, e1 = DEAD64, e2 = DEAD64, e3 = DEAD64;
            for (int j = jb; j < je; j++) {
                float prob = sprob[j * KP1 + lab];
                float l1 = fabsf(pq0[j] - t0) + fabsf(pq1[j] - t1) +
                           fabsf(pq2[j] - t2) + fabsf(pq3[j] - t3);
                float cosd = pqc[j] * tcc + pqs[j] * tss;
                float v = -2.f * prob + 5.f * l1 + 2.f * (1.f - cosd);
                unsigned long long k = ((unsigned long long)ford(v) << 32) | (unsigned)(q0 + j);
                if (k < e3) {
                    if (k < e0)      { e3 = e2; e2 = e1; e1 = e0; e0 = k; }
                    else if (k < e1) { e3 = e2; e2 = e1; e1 = k; }
                    else if (k < e2) { e3 = e2; e2 = k; }
                    else             { e3 = k; }
                }
            }
            size_t idx = (((size_t)b * NT + tile) * MM + m) * 4;
            g_top[idx + 0] = e0; g_top[idx + 1] = e1;
            g_top[idx + 2] = e2; g_top[idx + 3] = e3;
        }
        __threadfence();
        __syncthreads();
        if (tid == 0) atomicAdd(&g_ready[b], 1u);

    } else {
        // ================= MATCH BLOCK: image b ===============================
        int b = bid - BB * 4;
        int lane = tid & 31, wid = tid >> 5;
        unsigned long long (*ce)[4] = (unsigned long long(*)[4])smraw;   // 4 KB
        float* rmask = (float*)(smraw + 4096);                            // 4 KB
        short* sq  = (short*)(rmask + 1024);
        short* smi = sq + MM;
        float* sb80 = (float*)(smi + MM);                                 // QQ floats
        float* wsum = sb80 + QQ;
        float* buf  = wsum + 8;
        const float* C = g_costT + (size_t)b * MM * QQ;

        // wait for this image's 4 producers
        if (tid == 0) {
            while (*(volatile unsigned*)&g_ready[b] < 4u) __nanosleep(200);
            __threadfence();
        }
        __syncthreads();

        for (int q = tid; q < 1024; q += 256) rmask[q] = 0.f;

        // ---- merge 8 per-tile top-4 lists into exact global top-4 ----
        if (tid < MM) {
            const unsigned long long* p = g_top + ((size_t)b * NT * MM + tid) * 4;
            unsigned long long e0 = DEAD64, e1 = DEAD64, e2 = DEAD64, e3 = DEAD64;
#pragma unroll
            for (int t = 0; t < NT; t++) {
#pragma unroll
                for (int r = 0; r < 4; r++) {
                    unsigned long long k = p[(size_t)t * MM * 4 + r];
                    if (k < e3) {
                        if (k < e0)      { e3 = e2; e2 = e1; e1 = e0; e0 = k; }
                        else if (k < e1) { e3 = e2; e2 = e1; e1 = k; }
                        else if (k < e2) { e3 = e2; e2 = k; }
                        else             { e3 = k; }
                    }
                }
            }
            ce[tid][0] = e0; ce[tid][1] = e1; ce[tid][2] = e2; ce[tid][3] = e3;
        }
        __syncthreads();

        if (wid == 0) {
            // ========== R8 matching loop (proven fastest) =====================
            unsigned long long e[4][4];
#pragma unroll
            for (int g = 0; g < 4; g++)
#pragma unroll
                for (int r = 0; r < 4; r++) e[g][r] = ce[lane + 32 * g][r];

            int it = 0;
            while (it < MM) {
                int nc = 0;
                unsigned myrq = FULL;
                while (nc < 32 && it + nc < MM) {
                    unsigned long long best = DEAD64;
#pragma unroll
                    for (int g = 0; g < 4; g++) {
                        unsigned long long h = e[g][0];
                        unsigned long long k2 = ((h >> 32) << 17)
                                              | (((unsigned)h & 0x3ffu) << 7)
                                              | (unsigned)(lane + 32 * g);
                        if (k2 < best) best = k2;
                    }
                    unsigned hi = (unsigned)(best >> 17);
                    unsigned himin = __reduce_min_sync(FULL, hi);
                    unsigned lo = (hi == himin) ? (unsigned)(best & 0x1ffffu) : FULL;
                    unsigned lomin = __reduce_min_sync(FULL, lo);
                    unsigned qs = lomin >> 7;
                    int ms = (int)(lomin & 127u);
                    if (__ballot_sync(FULL, lane < nc && myrq == qs))
                        break;                    // winner's row already in batch
                    if (lane == nc) myrq = qs;
                    if (lane == 0) { sq[it + nc] = (short)qs; smi[it + nc] = (short)ms; }
                    if (lane == (ms & 31)) {
                        int g = ms >> 5;
                        e[g][0] = DEAD64; e[g][1] = DEAD64; e[g][2] = DEAD64; e[g][3] = DEAD64;
                    }
                    nc++;
                }
                it += nc;
                if (lane < nc) rmask[myrq] = INFF;
                __syncwarp();
                if (it >= MM) break;

                // advance heads whose row is now masked
                bool r0 = false, r1 = false, r2 = false, r3 = false;
#pragma unroll
                for (int g = 0; g < 4; g++) {
                    if (e[g][0] == DEAD64) continue;
                    if (rmask[(unsigned)e[g][0] & 0x3ffu] != 0.f) {
                        do {
                            e[g][0] = e[g][1]; e[g][1] = e[g][2]; e[g][2] = e[g][3]; e[g][3] = DEAD64;
                        } while (e[g][0] != DEAD64 &&
                                 rmask[(unsigned)e[g][0] & 0x3ffu] != 0.f);
                        if (e[g][0] == DEAD64) {
                            if (g == 0) r0 = true; else if (g == 1) r1 = true;
                            else if (g == 2) r2 = true; else r3 = true;
                        }
                    }
                }
                // rare: list exhausted -> exact cooperative column rescan
                if (__ballot_sync(FULL, r0 | r1 | r2 | r3)) {
#pragma unroll
                    for (int g = 0; g < 4; g++) {
                        bool rg = (g == 0) ? r0 : (g == 1) ? r1 : (g == 2) ? r2 : r3;
                        unsigned bal = __ballot_sync(FULL, rg);
                        while (bal) {
                            int c = __ffs(bal) - 1; bal &= bal - 1;
                            int mr = c + 32 * g;
                            const float* col = C + (size_t)mr * QQ;
                            float nv = INFF; int nq = 0x3ff;
#pragma unroll 7
                            for (int j = 0; j < 28; j++) {
                                int q2 = lane + 32 * j;
                                float v = col[q2] + rmask[q2];
                                if (v < nv) { nv = v; nq = q2; }
                            }
                            { int q2 = lane + 896; if (q2 < QQ) { float v = col[q2] + rmask[q2]; if (v < nv) { nv = v; nq = q2; } } }
                            unsigned uu = ford(nv);
                            unsigned um = __reduce_min_sync(FULL, uu);
                            unsigned qq = (uu == um) ? (unsigned)nq : FULL;
                            unsigned qmn = __reduce_min_sync(FULL, qq);
                            if (lane == c)
                                e[g][0] = ((unsigned long long)um << 32) | qmn;
                            __syncwarp();
                        }
                    }
                }
                __syncwarp();
            }
        } else {
            // ---- warps 1-7: CE baseline (coalesced b80 load) ----
            float base = 0.f;
            for (int q = tid - 32; q < QQ; q += 224) {
                float v = g_b80[b * QQ + q];
                sb80[q] = v;
                base += v;
            }
            for (int o = 16; o; o >>= 1) base += __shfl_xor_sync(FULL, base, o);
            if (lane == 0) wsum[wid] = 0.1f * base;
        }
        __syncthreads();

        // ---- matched corrections ----
        float corr = 0.f, sb = 0.f, sa = 0.f;
        if (tid < MM) {
            int q = sq[tid], m = smi[tid];
            int lab = labels[b * MM + m];
            int row = b * QQ + q;
            corr = (g_lse[row] - logits[(size_t)row * KP1 + lab]) - 0.1f * sb80[q];
            float H = sizes[b * 2 + 0], W = sizes[b * 2 + 1];
            const float* pb = pboxes + ((size_t)b * QQ + q) * 5;
            const float* tb = tboxes + ((size_t)b * MM + m) * 5;
            sb = fabsf(pb[0] - tb[0] / W) + fabsf(pb[1] - tb[1] / H) +
                 fabsf(pb[2] - tb[2] / W) + fabsf(pb[3] - tb[3] / H);
            sa = 1.f - cosf(pb[4] - tb[4]);
        }

        buf[tid] = corr; __syncthreads();
        for (int s = 128; s > 0; s >>= 1) { if (tid < s) buf[tid] += buf[tid + s]; __syncthreads(); }
        float numt = buf[0]; __syncthreads();
        buf[tid] = sb; __syncthreads();
        for (int s = 128; s > 0; s >>= 1) { if (tid < s) buf[tid] += buf[tid + s]; __syncthreads(); }
        float sbt = buf[0]; __syncthreads();
        buf[tid] = sa; __syncthreads();
        for (int s = 128; s > 0; s >>= 1) { if (tid < s) buf[tid] += buf[tid + s]; __syncthreads(); }
        float sat = buf[0];

        if (tid == 0) {
#pragma unroll
            for (int w = 1; w < 8; w++) numt += wsum[w];
            atomicAdd(&g_acc[0], numt);
            atomicAdd(&g_acc[1], sbt);
            atomicAdd(&g_acc[2], sat);
            __threadfence();
            unsigned done = atomicAdd(&g_done, 1u);
            if (done == BB - 1) {
                const float den = 0.1f * (QQ - MM) + (float)MM;  // 205.2 per image
                float lc = g_acc[0] / (den * BB);
                float lb = g_acc[1] * 5.f / (float)(MM * 4 * BB);
                float la = g_acc[2] * 2.f / (float)(MM * BB);
                out[0] = lc;
                out[1] = lb;
                out[2] = la;
                out[3] = lc + lb + la;
                // reset state for the next (graph-replayed) launch
                g_acc[0] = 0.f; g_acc[1] = 0.f; g_acc[2] = 0.f;
                g_done = 0u;
            }
            g_ready[b] = 0u;                  // per-image reset for next launch
        }
    }
}

extern "C" void kernel_launch(void* const* d_in, const int* in_sizes, int n_in,
                              void* d_out, int out_size) {
    const float* logits = (const float*)d_in[0];   // [B,Q,81]
    const float* pboxes = (const float*)d_in[1];   // [B,Q,5]
    const float* tboxes = (const float*)d_in[2];   // [B,M,5]
    const float* sizes  = (const float*)d_in[3];   // [B,2]
    const int*   labels = (const int*)d_in[4];     // [B,M]
    float* out = (float*)d_out;

    cudaFuncSetAttribute(k_fused, cudaFuncAttributeMaxDynamicSharedMemorySize,
                         SMEM_TOTAL);
    k_fused<<<BB * 4 + BB, 256, SMEM_TOTAL>>>(logits, pboxes, tboxes, sizes,
                                              labels, out);
}